// round 1
// baseline (speedup 1.0000x reference)
#include <cuda_runtime.h>
#include <cstdint>

#define NB 32
#define NS 1024
#define NI 256
#define NH 512
#define NO 256

// Scratch: device globals (no allocations allowed)
__device__ float    g_inp_cur[(size_t)NB * NS * NH];     // 64 MB
__device__ unsigned g_spike_bits[(size_t)NB * NS * 16];  // 2 MB packed spikes

// ---------------------------------------------------------------------------
// K1: inp_cur[b*s, h] = X[b*s, i] @ Wi[i, h]   (fp32 SIMT tiled GEMM)
// ---------------------------------------------------------------------------
__global__ __launch_bounds__(256) void k1_gemm(const float* __restrict__ X,
                                               const float* __restrict__ Wi) {
    __shared__ float As[64][33];  // padded to kill bank conflicts
    __shared__ float Bs[32][64];
    const int m0 = blockIdx.y * 64, n0 = blockIdx.x * 64;
    const int tid = threadIdx.x;
    const int tm = tid >> 4, tn = tid & 15;

    float acc[4][4];
#pragma unroll
    for (int i = 0; i < 4; i++)
#pragma unroll
        for (int j = 0; j < 4; j++) acc[i][j] = 0.f;

    for (int k0 = 0; k0 < NI; k0 += 32) {
#pragma unroll
        for (int e = 0; e < 8; e++) {
            int idx = tid + e * 256;  // i = idx>>5 (row), j = idx&31 (k)
            As[idx >> 5][idx & 31] = X[(size_t)(m0 + (idx >> 5)) * NI + k0 + (idx & 31)];
        }
#pragma unroll
        for (int e = 0; e < 8; e++) {
            int idx = tid + e * 256;  // j = idx>>6 (k), c = idx&63 (col)
            Bs[idx >> 6][idx & 63] = Wi[(size_t)(k0 + (idx >> 6)) * NH + n0 + (idx & 63)];
        }
        __syncthreads();
#pragma unroll
        for (int k = 0; k < 32; k++) {
            float a[4];
#pragma unroll
            for (int i = 0; i < 4; i++) a[i] = As[tm * 4 + i][k];
            float4 bv = *reinterpret_cast<const float4*>(&Bs[k][tn * 4]);
            float b[4] = {bv.x, bv.y, bv.z, bv.w};
#pragma unroll
            for (int i = 0; i < 4; i++)
#pragma unroll
                for (int j = 0; j < 4; j++) acc[i][j] += a[i] * b[j];
        }
        __syncthreads();
    }
#pragma unroll
    for (int i = 0; i < 4; i++) {
        float4 v = make_float4(acc[i][0], acc[i][1], acc[i][2], acc[i][3]);
        *reinterpret_cast<float4*>(
            &g_inp_cur[(size_t)(m0 + tm * 4 + i) * NH + n0 + tn * 4]) = v;
    }
}

// ---------------------------------------------------------------------------
// Warp-cooperative bit compaction: 16 mask words (512 bits) -> ascending index
// list (u16). lane l handles 16-bit half (l&1) of word (l>>1). Deterministic.
// ---------------------------------------------------------------------------
__device__ __forceinline__ int compact_warp(const unsigned* words, unsigned short* list) {
    const int lane = threadIdx.x & 31;
    unsigned w = words[lane >> 1];
    unsigned m = (lane & 1) ? (w >> 16) : (w & 0xFFFFu);
    int cnt = __popc(m);
    int sc = cnt;
#pragma unroll
    for (int d = 1; d < 32; d <<= 1) {
        int v = __shfl_up_sync(0xffffffffu, sc, d);
        if (lane >= d) sc += v;
    }
    int total = __shfl_sync(0xffffffffu, sc, 31);
    int off = sc - cnt;  // exclusive prefix
    int base = (lane >> 1) * 32 + (lane & 1) * 16;
    while (m) {
        int j = __ffs(m) - 1;
        m &= m - 1;
        list[off++] = (unsigned short)(base + j);
    }
    return total;
}

__device__ __forceinline__ unsigned smem_u32(const void* p) {
    return (unsigned)__cvta_generic_to_shared(p);
}
__device__ __forceinline__ void st_cluster_u32(unsigned laddr, unsigned rank, unsigned val) {
    asm volatile(
        "{\n\t.reg .b32 ra;\n\t"
        "mapa.shared::cluster.u32 ra, %0, %1;\n\t"
        "st.shared::cluster.u32 [ra], %2;\n\t}"
        :: "r"(laddr), "r"(rank), "r"(val) : "memory");
}
__device__ __forceinline__ void cluster_sync_() {
    asm volatile("barrier.cluster.arrive.aligned;" ::: "memory");
    asm volatile("barrier.cluster.wait.aligned;" ::: "memory");
}

// ---------------------------------------------------------------------------
// K2: persistent cluster scan. 16 clusters x 8 CTAs. Cluster c owns batches
// {2c, 2c+1}. CTA rank r holds W_lat columns [64r, 64r+64) in smem (128 KB).
// Per step: compact spike masks -> sparse column sums -> membrane update ->
// ballot spikes -> push 64 bits to all 8 peers (DSMEM) -> cluster barrier.
// ---------------------------------------------------------------------------
#define SCAN_SMEM (512 * 64 * 4 + 2 * 2 * 16 * 4 + 2 * 512 * 2 + 128 * 4 + 16)

__global__ void __cluster_dims__(8, 1, 1) __launch_bounds__(256, 1)
k2_scan(const float* __restrict__ Wl, const float* __restrict__ thr) {
    extern __shared__ char smem[];
    float*          Wsm     = (float*)smem;                               // 512*64 fp32
    unsigned*       s_masks = (unsigned*)(smem + 512 * 64 * 4);           // [2 buf][2 b][16]
    unsigned short* s_list  = (unsigned short*)((char*)s_masks + 2 * 2 * 16 * 4);  // [2][512]
    float*          s_acc   = (float*)((char*)s_list + 2 * 512 * 2);      // [128]
    int*            s_cnt   = (int*)((char*)s_acc + 128 * 4);             // [2]

    const int tid  = threadIdx.x;
    const unsigned rank = blockIdx.x & 7;
    const int cid  = blockIdx.x >> 3;

    // Load W_lat column slice [512 rows x 64 cols]
    for (int idx = tid; idx < 512 * 64; idx += 256)
        Wsm[idx] = Wl[(size_t)(idx >> 6) * NH + rank * 64 + (idx & 63)];
    if (tid < 64) s_masks[tid] = 0u;

    const int half = tid >> 7;        // which half of the spike list
    const int b    = (tid >> 6) & 1;  // local batch
    const int col  = tid & 63;        // local neuron column
    const int warp = tid >> 5;
    const int lane = tid & 31;

    float mp = 0.f;
    int refrac = 0;
    float th = 0.f;
    const float* icp = nullptr;
    if (tid < 128) {
        th  = thr[rank * 64 + col];
        icp = g_inp_cur + (size_t)(cid * 2 + b) * NS * NH + rank * 64 + col;
    }
    const unsigned masks_saddr = smem_u32(s_masks);
    const size_t bits_base = (size_t)(cid * 2) * NS * 16;

    cluster_sync_();  // all CTAs initialized before any remote pushes / reads

    for (int t = 0; t < NS; t++) {
        const int wbuf = t & 1, rbuf = wbuf ^ 1;
        float ic = 0.f;
        if (tid < 128) ic = icp[(size_t)t * NH];  // prefetch input current

        // Compact previous-step spike masks (warp0: batch0, warp1: batch1)
        if (warp < 2) {
            int total = compact_warp(&s_masks[(rbuf * 2 + warp) * 16], &s_list[warp * 512]);
            if (lane == 0) s_cnt[warp] = total;
        }
        __syncthreads();

        // Sparse lateral accumulation over my half of the active list
        float part;
        {
            const int total = s_cnt[b];
            const int mid = (total + 1) >> 1;
            const int i0 = half ? mid : 0;
            const int i1 = half ? total : mid;
            const unsigned short* L = &s_list[b * 512];
            float a0 = 0.f, a1 = 0.f;
            int i = i0;
            for (; i + 1 < i1; i += 2) {
                a0 += Wsm[(int)L[i] * 64 + col];
                a1 += Wsm[(int)L[i + 1] * 64 + col];
            }
            if (i < i1) a0 += Wsm[(int)L[i] * 64 + col];
            part = a0 + a1;
        }
        if (tid >= 128) s_acc[tid & 127] = part;
        __syncthreads();

        if (tid < 128) {
            float lat = part + s_acc[tid];
            float nmp = fmaf(0.95f, mp, ic) - lat;
            if (refrac > 0) nmp = 0.f;
            refrac = (refrac > 0) ? refrac - 1 : 0;
            bool sp = (nmp >= th);
            if (sp) { nmp = 0.f; refrac = 2; }
            mp = nmp;
            unsigned bal = __ballot_sync(0xffffffffu, sp);
            if (lane == 0) {
                const int wsub = warp & 1;  // low/high 32 cols of my 64
                g_spike_bits[bits_base + (size_t)b * NS * 16 + (size_t)t * 16 +
                             rank * 2 + wsub] = bal;
                unsigned la = masks_saddr +
                              ((unsigned)(wbuf * 2 + b) * 16 + rank * 2 + wsub) * 4u;
#pragma unroll
                for (unsigned rk = 0; rk < 8; rk++) st_cluster_u32(la, rk, bal);
            }
        }
        cluster_sync_();  // release my pushes, acquire peers' pushes
    }
}

// ---------------------------------------------------------------------------
// K3: out[b*s, o] = spikes[b*s, h] @ Wo[h, o], sparse from packed bits.
// Grid = 4 col-groups x 37 row-chunks. Wo column slice resident in smem.
// ---------------------------------------------------------------------------
#define K3_SMEM (512 * 64 * 4 + 4 * 512 * 2)

__global__ __launch_bounds__(256, 1) void k3_out(const float* __restrict__ Wo,
                                                 float* __restrict__ out) {
    extern __shared__ char smem[];
    float*          Ws    = (float*)smem;                       // 512 x 64 slice
    unsigned short* lists = (unsigned short*)(smem + 512 * 64 * 4);  // [4][512]
    __shared__ int cnts[4];

    const int tid = threadIdx.x;
    const int g = blockIdx.x & 3, chunk = blockIdx.x >> 2;
    const int rs = tid >> 6, col = tid & 63;

    for (int idx = tid; idx < 512 * 64; idx += 256)
        Ws[idx] = Wo[(size_t)(idx >> 6) * NO + g * 64 + (idx & 63)];
    __syncthreads();

    const int r0 = chunk * 886;
    const int r1 = min(r0 + 886, NB * NS);
    for (int rb = r0; rb < r1; rb += 4) {
        const int r = rb + rs;
        const bool valid = (r < r1);
        if (((tid >> 5) & 1) == 0 && valid) {  // even warp of each row-slot compacts
            int total = compact_warp(&g_spike_bits[(size_t)r * 16], &lists[rs * 512]);
            if ((tid & 31) == 0) cnts[rs] = total;
        }
        __syncthreads();
        if (valid) {
            const int n = cnts[rs];
            const unsigned short* L = &lists[rs * 512];
            float a0 = 0.f, a1 = 0.f;
            int i = 0;
            for (; i + 1 < n; i += 2) {
                a0 += Ws[(int)L[i] * 64 + col];
                a1 += Ws[(int)L[i + 1] * 64 + col];
            }
            if (i < n) a0 += Ws[(int)L[i] * 64 + col];
            out[(size_t)r * NO + g * 64 + col] = a0 + a1;
        }
        __syncthreads();
    }
}

// ---------------------------------------------------------------------------
extern "C" void kernel_launch(void* const* d_in, const int* in_sizes, int n_in,
                              void* d_out, int out_size) {
    const float* x  = (const float*)d_in[0];
    const float* wi = (const float*)d_in[1];
    const float* wl = (const float*)d_in[2];
    const float* wo = (const float*)d_in[3];
    const float* th = (const float*)d_in[4];
    float* out = (float*)d_out;

    cudaFuncSetAttribute(k2_scan, cudaFuncAttributeMaxDynamicSharedMemorySize, SCAN_SMEM);
    cudaFuncSetAttribute(k3_out, cudaFuncAttributeMaxDynamicSharedMemorySize, K3_SMEM);

    dim3 g1(NH / 64, (NB * NS) / 64);
    k1_gemm<<<g1, 256>>>(x, wi);
    k2_scan<<<128, 256, SCAN_SMEM>>>(wl, th);
    k3_out<<<148, 256, K3_SMEM>>>(wo, out);
}